// round 8
// baseline (speedup 1.0000x reference)
#include <cuda_runtime.h>

#define N_EMBED   64
#define BPS       6
#define NSM       152
#define NBLK      (NSM * BPS)              // 912
#define NTHREADS  128
#define NGROUPS   (NBLK * NTHREADS / 8)    // 14592 eight-lane groups

// Per-block likelihood partials [codeword][block] + launch-persistent ticket.
__device__ __align__(16) float g_part[N_EMBED * NBLK];
__device__ unsigned int g_tick;

__device__ __forceinline__ float ex2f(float x) { float r; asm("ex2.approx.f32 %0,%1;" : "=f"(r) : "f"(x)); return r; }
__device__ __forceinline__ float rcpf(float x) { float r; asm("rcp.approx.f32 %0,%1;" : "=f"(r) : "f"(x)); return r; }

// One point's pipeline for this lane's 8 codewords (8-lane group).
// Scalar ops only; reductions via 3-level xor shuffles within the group.
__device__ __forceinline__ void point_body(
    float2 p, int n, int base, int lane_in_grp, unsigned gmask,
    const float cx[8], const float cy[8], const float cz[8],
    float acc[8], const float2* __restrict__ s_emb,
    float2* __restrict__ oq)
{
    // --- logits: l[k] = px*cx + py*cy + cz ---
    float l[8];
#pragma unroll
    for (int k = 0; k < 8; k++)
        l[k] = fmaf(p.x, cx[k], fmaf(p.y, cy[k], cz[k]));

    // --- exact max: FMNMX tree + 3-level cross-lane ---
    float m4a = fmaxf(l[0], l[1]), m4b = fmaxf(l[2], l[3]);
    float m4c = fmaxf(l[4], l[5]), m4d = fmaxf(l[6], l[7]);
    float m   = fmaxf(fmaxf(m4a, m4b), fmaxf(m4c, m4d));
    m = fmaxf(m, __shfl_xor_sync(gmask, m, 1));
    m = fmaxf(m, __shfl_xor_sync(gmask, m, 2));
    m = fmaxf(m, __shfl_xor_sync(gmask, m, 4));

    // --- shifted logits (shared by argmax encode and exp) ---
    // d[k] = l[k]-m <= 0, d == +0 exactly at the max; umin over (bits(d)|idx):
    // negatives carry the sign bit and lose; ties pick the smallest index
    // (matches jnp.argmax first-occurrence).
    float d[8];
#pragma unroll
    for (int k = 0; k < 8; k++) d[k] = l[k] - m;

    unsigned e4[4];
#pragma unroll
    for (int i = 0; i < 4; i++)
        e4[i] = umin(__float_as_uint(d[2 * i])     | (unsigned)(base + 2 * i),
                     __float_as_uint(d[2 * i + 1]) | (unsigned)(base + 2 * i + 1));
    unsigned enc = umin(umin(e4[0], e4[1]), umin(e4[2], e4[3]));
    enc = umin(enc, __shfl_xor_sync(gmask, enc, 1));
    enc = umin(enc, __shfl_xor_sync(gmask, enc, 2));
    enc = umin(enc, __shfl_xor_sync(gmask, enc, 4));

    // --- exps + pairwise sum ---
    float v[8];
#pragma unroll
    for (int k = 0; k < 8; k++) v[k] = ex2f(d[k]);

    float s4a = v[0] + v[1], s4b = v[2] + v[3];
    float s4c = v[4] + v[5], s4d = v[6] + v[7];
    float ssum = (s4a + s4b) + (s4c + s4d);
    ssum += __shfl_xor_sync(gmask, ssum, 1);
    ssum += __shfl_xor_sync(gmask, ssum, 2);
    ssum += __shfl_xor_sync(gmask, ssum, 4);

    const float inv = rcpf(ssum);
#pragma unroll
    for (int k = 0; k < 8; k++)
        acc[k] = fmaf(v[k], inv, acc[k]);

    // hard quantize (straight-through forward value = argmax codeword)
    if (lane_in_grp == 0)
        oq[n] = s_emb[enc];
}

__global__ __launch_bounds__(NTHREADS, BPS)
void jsccq_main(const float* __restrict__ x, const float* __restrict__ embed,
                float* __restrict__ out_q, float* __restrict__ out_like,
                int npts, float invN) {
    __shared__ float  s_cx[N_EMBED], s_cy[N_EMBED], s_cz[N_EMBED];
    __shared__ float2 s_emb[N_EMBED];
    __shared__ float  s_like[N_EMBED];
    __shared__ unsigned s_isLast;

    const int tid = threadIdx.x;
    if (tid < N_EMBED) {
        const float s = 10.0f * 1.4426950408889634f;   // sigma * log2(e)
        float ex = embed[2 * tid + 0];
        float ey = embed[2 * tid + 1];
        s_cx[tid]  = 2.0f * s * ex;
        s_cy[tid]  = 2.0f * s * ey;
        s_cz[tid]  = -s * (ex * ex + ey * ey);
        s_emb[tid]  = make_float2(ex, ey);
        s_like[tid] = 0.0f;
    }
    __syncthreads();

    const int lane_in_grp = tid & 7;
    const int base = lane_in_grp * 8;
    const unsigned gmask = 0xFFu << ((tid & 31) & ~7);   // 8-lane group mask

    // Register-resident codebook slice (24 regs).
    float cx[8], cy[8], cz[8];
#pragma unroll
    for (int k = 0; k < 8; k++) {
        cx[k] = s_cx[base + k];
        cy[k] = s_cy[base + k];
        cz[k] = s_cz[base + k];
    }

    float acc[8];
#pragma unroll
    for (int k = 0; k < 8; k++) acc[k] = 0.0f;

    const float2* __restrict__ pts = reinterpret_cast<const float2*>(x);
    float2* __restrict__       oq  = reinterpret_cast<float2*>(out_q);

    const int gid        = (blockIdx.x * NTHREADS + tid) >> 3;
    const int full_iters = npts / NGROUPS;               // unguarded main loop
    const int rem        = npts - full_iters * NGROUPS;
    const bool has_tail  = (gid < rem);

    int    n = gid;
    float2 p = pts[gid];

    for (int it = 0; it < full_iters; it++) {
        const int  nn       = n + NGROUPS;
        const bool has_next = (it + 1 < full_iters) || has_tail;
        float2 pn = has_next ? pts[nn] : make_float2(0.0f, 0.0f);  // prefetch

        point_body(p, n, base, lane_in_grp, gmask, cx, cy, cz, acc, s_emb, oq);

        p = pn;
        n = nn;
    }
    if (has_tail)
        point_body(p, n, base, lane_in_grp, gmask, cx, cy, cz, acc, s_emb, oq);

    // --- block-level likelihood reduction ---
    // After xor 8,16: lane L of each warp holds the sum over lanes sharing
    // (L & 7), i.e. the same 8-codeword slice.
#pragma unroll
    for (int k = 0; k < 8; k++) {
        float vv = acc[k];
        vv += __shfl_xor_sync(0xffffffffu, vv, 8);
        vv += __shfl_xor_sync(0xffffffffu, vv, 16);
        if ((tid & 31) < 8)
            atomicAdd(&s_like[base + k], vv);
    }
    __syncthreads();
    if (tid < N_EMBED)
        g_part[tid * NBLK + blockIdx.x] = s_like[tid];
    __threadfence();
    __syncthreads();

    // --- last-arriving block reduces partials (replay-safe via mod) ---
    if (tid == 0) {
        unsigned t = atomicAdd(&g_tick, 1u);
        s_isLast = ((t % NBLK) == (NBLK - 1)) ? 1u : 0u;
    }
    __syncthreads();

    if (s_isLast && out_like != nullptr) {
        __threadfence();
        const int cw = tid >> 1;                     // 2 threads per codeword
        const float4* row = reinterpret_cast<const float4*>(&g_part[cw * NBLK])
                          + (tid & 1) * (NBLK / 8);  // 114 float4 each
        float s = 0.0f;
#pragma unroll 6
        for (int i = 0; i < NBLK / 8; i++) {
            float4 q = row[i];
            s += (q.x + q.y) + (q.z + q.w);
        }
        s += __shfl_xor_sync(0xffffffffu, s, 1);
        if ((tid & 1) == 0)
            out_like[cw] = s * invN;
    }
}

extern "C" void kernel_launch(void* const* d_in, const int* in_sizes, int n_in,
                              void* d_out, int out_size) {
    const float* x     = (const float*)d_in[0];   // [64,32,32,32] fp32
    const float* embed = (const float*)d_in[1];   // [64,2]        fp32
    float* out = (float*)d_out;

    const int npts = in_sizes[0] / 2;             // 1,048,576 points

    float* out_like = (out_size >= 2 * npts + N_EMBED) ? (out + 2 * npts) : nullptr;

    jsccq_main<<<NBLK, NTHREADS>>>(x, embed, out, out_like, npts,
                                   1.0f / (float)npts);
}